// round 1
// baseline (speedup 1.0000x reference)
#include <cuda_runtime.h>
#include <stdint.h>

#define D_IN   256
#define D_HID  64
#define D_EMB  32
#define MAX_NODES 100000

// Scratch (static __device__ — no allocation allowed)
__device__ float g_H [MAX_NODES * D_HID];   // x @ W1
__device__ float g_S1[MAX_NODES * D_HID];   // A @ H
__device__ float g_Z1[MAX_NODES * D_EMB];   // relu(S1+b1) @ W2
__device__ float g_S2[MAX_NODES * D_EMB];   // A @ Z1

// ---------------------------------------------------------------------------
// Zero the two scatter targets
// ---------------------------------------------------------------------------
__global__ void zero_kernel(int n64, int n32) {
    int i = blockIdx.x * blockDim.x + threadIdx.x;
    float4 z = make_float4(0.f, 0.f, 0.f, 0.f);
    int n64_4 = n64 >> 2;
    int n32_4 = n32 >> 2;
    if (i < n64_4) ((float4*)g_S1)[i] = z;
    if (i < n32_4) ((float4*)g_S2)[i] = z;
}

// ---------------------------------------------------------------------------
// GEMM1: H = x @ W1   [n,256] @ [256,64]
// Block tile 64x64, k-chunks of 64, thread tile 4x4, 256 threads.
// ---------------------------------------------------------------------------
__global__ __launch_bounds__(256) void gemm1_kernel(
    const float* __restrict__ x, const float* __restrict__ W1, int n)
{
    __shared__ float xs[64][65];
    __shared__ float ws[64][64];

    int tid = threadIdx.x;
    int ty = tid >> 4;          // 0..15 -> 4 rows each
    int tx = tid & 15;          // 0..15 -> 4 cols each
    int row_base = blockIdx.x * 64;

    float acc00=0,acc01=0,acc02=0,acc03=0;
    float acc10=0,acc11=0,acc12=0,acc13=0;
    float acc20=0,acc21=0,acc22=0,acc23=0;
    float acc30=0,acc31=0,acc32=0,acc33=0;

    for (int kc = 0; kc < D_IN; kc += 64) {
        // load x tile (64 rows x 64 k), float4 per thread x4
        #pragma unroll
        for (int l = 0; l < 4; l++) {
            int flat = tid + l * 256;        // float4 index, 1024 total
            int r    = flat >> 4;            // 16 float4 per row
            int c4   = flat & 15;
            float4 v = make_float4(0.f,0.f,0.f,0.f);
            int grow = row_base + r;
            if (grow < n)
                v = *(const float4*)(x + (size_t)grow * D_IN + kc + c4 * 4);
            xs[r][c4*4+0] = v.x; xs[r][c4*4+1] = v.y;
            xs[r][c4*4+2] = v.z; xs[r][c4*4+3] = v.w;
        }
        // load W1 chunk (contiguous 64x64)
        #pragma unroll
        for (int l = 0; l < 4; l++) {
            int flat = tid + l * 256;
            ((float4*)&ws[0][0])[flat] =
                *(const float4*)(W1 + (size_t)kc * 64 + (size_t)flat * 4);
        }
        __syncthreads();

        #pragma unroll 16
        for (int kk = 0; kk < 64; kk++) {
            float a0 = xs[ty*4+0][kk];
            float a1 = xs[ty*4+1][kk];
            float a2 = xs[ty*4+2][kk];
            float a3 = xs[ty*4+3][kk];
            float4 b = *(float4*)&ws[kk][tx*4];
            acc00 += a0*b.x; acc01 += a0*b.y; acc02 += a0*b.z; acc03 += a0*b.w;
            acc10 += a1*b.x; acc11 += a1*b.y; acc12 += a1*b.z; acc13 += a1*b.w;
            acc20 += a2*b.x; acc21 += a2*b.y; acc22 += a2*b.z; acc23 += a2*b.w;
            acc30 += a3*b.x; acc31 += a3*b.y; acc32 += a3*b.z; acc33 += a3*b.w;
        }
        __syncthreads();
    }

    int col = tx * 4;
    int r0 = row_base + ty*4;
    if (r0 + 0 < n) *(float4*)(g_H + (size_t)(r0+0)*D_HID + col) = make_float4(acc00,acc01,acc02,acc03);
    if (r0 + 1 < n) *(float4*)(g_H + (size_t)(r0+1)*D_HID + col) = make_float4(acc10,acc11,acc12,acc13);
    if (r0 + 2 < n) *(float4*)(g_H + (size_t)(r0+2)*D_HID + col) = make_float4(acc20,acc21,acc22,acc23);
    if (r0 + 3 < n) *(float4*)(g_H + (size_t)(r0+3)*D_HID + col) = make_float4(acc30,acc31,acc32,acc33);
}

// ---------------------------------------------------------------------------
// SpMM d=64: S1[dst] += val * H[src]. 16 threads per edge, float4 + red.v4.
// ---------------------------------------------------------------------------
__device__ __forceinline__ void red_add_v4(float* p, float4 v) {
    asm volatile("red.global.add.v4.f32 [%0], {%1,%2,%3,%4};"
                 :: "l"(p), "f"(v.x), "f"(v.y), "f"(v.z), "f"(v.w)
                 : "memory");
}

__global__ __launch_bounds__(256) void spmm64_kernel(
    const int* __restrict__ src, const int* __restrict__ dst,
    const float* __restrict__ val, int nnz)
{
    int t = blockIdx.x * blockDim.x + threadIdx.x;
    int e = t >> 4;
    int c = t & 15;
    if (e >= nnz) return;
    int   s = __ldg(src + e);
    int   d = __ldg(dst + e);
    float v = __ldg(val + e);
    float4 h = __ldg((const float4*)(g_H + (size_t)s * D_HID) + c);
    red_add_v4(g_S1 + (size_t)d * D_HID + c * 4,
               make_float4(v*h.x, v*h.y, v*h.z, v*h.w));
}

// ---------------------------------------------------------------------------
// GEMM2: Z1 = relu(S1 + b1) @ W2   [n,64] @ [64,32]
// Block tile 64 rows x 32 cols, thread tile 2x4, 256 threads, one k-pass.
// ---------------------------------------------------------------------------
__global__ __launch_bounds__(256) void gemm2_kernel(
    const float* __restrict__ b1, const float* __restrict__ W2, int n)
{
    __shared__ float zs[64][65];
    __shared__ float ws[64][32];

    int tid = threadIdx.x;
    int row_base = blockIdx.x * 64;

    // load S1 tile (contiguous 64x64 = 1024 float4), apply relu(+b1)
    #pragma unroll
    for (int l = 0; l < 4; l++) {
        int flat = tid + l * 256;
        int r  = flat >> 4;
        int c4 = flat & 15;
        float4 v = make_float4(0.f,0.f,0.f,0.f);
        if (row_base + r < n)
            v = *(const float4*)(g_S1 + (size_t)row_base * D_HID + (size_t)flat * 4);
        float4 bb = __ldg((const float4*)b1 + c4);
        v.x = fmaxf(v.x + bb.x, 0.f);
        v.y = fmaxf(v.y + bb.y, 0.f);
        v.z = fmaxf(v.z + bb.z, 0.f);
        v.w = fmaxf(v.w + bb.w, 0.f);
        zs[r][c4*4+0] = v.x; zs[r][c4*4+1] = v.y;
        zs[r][c4*4+2] = v.z; zs[r][c4*4+3] = v.w;
    }
    // load W2 (64x32 = 512 float4)
    #pragma unroll
    for (int l = 0; l < 2; l++) {
        int flat = tid + l * 256;
        ((float4*)&ws[0][0])[flat] = __ldg((const float4*)W2 + flat);
    }
    __syncthreads();

    int ty = tid >> 3;       // 0..31 -> 2 rows each
    int tx = tid & 7;        // 0..7  -> 4 cols each
    int col = tx * 4;

    float a00=0,a01=0,a02=0,a03=0;
    float a10=0,a11=0,a12=0,a13=0;

    #pragma unroll 16
    for (int kk = 0; kk < 64; kk++) {
        float z0 = zs[ty*2+0][kk];
        float z1 = zs[ty*2+1][kk];
        float4 b = *(float4*)&ws[kk][col];
        a00 += z0*b.x; a01 += z0*b.y; a02 += z0*b.z; a03 += z0*b.w;
        a10 += z1*b.x; a11 += z1*b.y; a12 += z1*b.z; a13 += z1*b.w;
    }

    int r0 = row_base + ty*2;
    if (r0 + 0 < n) *(float4*)(g_Z1 + (size_t)(r0+0)*D_EMB + col) = make_float4(a00,a01,a02,a03);
    if (r0 + 1 < n) *(float4*)(g_Z1 + (size_t)(r0+1)*D_EMB + col) = make_float4(a10,a11,a12,a13);
}

// ---------------------------------------------------------------------------
// SpMM d=32: S2[dst] += val * Z1[src]. 8 threads per edge.
// ---------------------------------------------------------------------------
__global__ __launch_bounds__(256) void spmm32_kernel(
    const int* __restrict__ src, const int* __restrict__ dst,
    const float* __restrict__ val, int nnz)
{
    int t = blockIdx.x * blockDim.x + threadIdx.x;
    int e = t >> 3;
    int c = t & 7;
    if (e >= nnz) return;
    int   s = __ldg(src + e);
    int   d = __ldg(dst + e);
    float v = __ldg(val + e);
    float4 h = __ldg((const float4*)(g_Z1 + (size_t)s * D_EMB) + c);
    red_add_v4(g_S2 + (size_t)d * D_EMB + c * 4,
               make_float4(v*h.x, v*h.y, v*h.z, v*h.w));
}

// ---------------------------------------------------------------------------
// Decoder: scores[e] = dot(S2[src]+b2, S2[dst]+b2), d=32. 8 threads/edge.
// ---------------------------------------------------------------------------
__global__ __launch_bounds__(256) void decoder_kernel(
    const int* __restrict__ edge_index, const float* __restrict__ b2,
    float* __restrict__ out, int ne)
{
    int t = blockIdx.x * blockDim.x + threadIdx.x;
    int e = t >> 3;
    int c = t & 7;
    bool active = (e < ne);
    int ec = active ? e : (ne - 1);    // clamp so all lanes participate in shfl

    int s = __ldg(edge_index + ec);
    int d = __ldg(edge_index + ne + ec);
    float4 bb = __ldg((const float4*)b2 + c);
    float4 a = __ldg((const float4*)(g_S2 + (size_t)s * D_EMB) + c);
    float4 b = __ldg((const float4*)(g_S2 + (size_t)d * D_EMB) + c);

    float p = (a.x + bb.x) * (b.x + bb.x)
            + (a.y + bb.y) * (b.y + bb.y)
            + (a.z + bb.z) * (b.z + bb.z)
            + (a.w + bb.w) * (b.w + bb.w);

    p += __shfl_xor_sync(0xFFFFFFFFu, p, 1);
    p += __shfl_xor_sync(0xFFFFFFFFu, p, 2);
    p += __shfl_xor_sync(0xFFFFFFFFu, p, 4);

    if (active && c == 0) out[e] = p;
}

// ---------------------------------------------------------------------------
extern "C" void kernel_launch(void* const* d_in, const int* in_sizes, int n_in,
                              void* d_out, int out_size)
{
    const float* x         = (const float*)d_in[0];
    const int*   adj_src   = (const int*)  d_in[1];
    const int*   adj_dst   = (const int*)  d_in[2];
    const float* adj_val   = (const float*)d_in[3];
    const int*   edge_idx  = (const int*)  d_in[4];
    const float* W1        = (const float*)d_in[5];
    const float* b1        = (const float*)d_in[6];
    const float* W2        = (const float*)d_in[7];
    /* const float* b2 */
    const float* b2        = (const float*)d_in[8];
    float*       out       = (float*)d_out;

    int n   = in_sizes[0] / D_IN;     // nodes
    int nnz = in_sizes[3];            // adjacency nnz
    int ne  = in_sizes[4] / 2;        // edges to score
    (void)n_in; (void)out_size;

    // zero scatter targets
    {
        int n4 = (n * D_HID) >> 2;    // larger of the two
        int blocks = (n4 + 255) / 256;
        zero_kernel<<<blocks, 256>>>(n * D_HID, n * D_EMB);
    }
    // GEMM1
    gemm1_kernel<<<(n + 63) / 64, 256>>>(x, W1, n);
    // SpMM1 (d=64)
    {
        long long total = (long long)nnz * 16;
        int blocks = (int)((total + 255) / 256);
        spmm64_kernel<<<blocks, 256>>>(adj_src, adj_dst, adj_val, nnz);
    }
    // GEMM2 (fused relu + b1)
    gemm2_kernel<<<(n + 63) / 64, 256>>>(b1, W2, n);
    // SpMM2 (d=32)
    {
        long long total = (long long)nnz * 8;
        int blocks = (int)((total + 255) / 256);
        spmm32_kernel<<<blocks, 256>>>(adj_src, adj_dst, adj_val, nnz);
    }
    // Decoder
    {
        long long total = (long long)ne * 8;
        int blocks = (int)((total + 255) / 256);
        decoder_kernel<<<blocks, 256>>>(edge_idx, b2, out, ne);
    }
}